// round 3
// baseline (speedup 1.0000x reference)
#include <cuda_runtime.h>

// Problem constants
#define BGR   8
#define NPTS  2048
#define NTOT  (BGR*NPTS)      // 16384
#define FIN   64
#define KNB   32
#define MS    512             // fps samples per graph
#define H1D   128
#define H2D   256
#define GOUTD 256
#define R2V   0.01f

// Scratch (static device globals — no runtime allocation)
__device__ float g_P[NTOT*H1D];     // x @ W1[:64] + b1   (8 MB)
__device__ int   g_nbr[NTOT*KNB];   // global neighbor indices
__device__ int   g_cnt[NTOT];       // valid neighbor count (<=32)
__device__ float g_agg[NTOT*H2D];   // max-aggregated features (16 MB)
__device__ int   g_fps[BGR*MS];     // local fps indices per graph

// ---------------------------------------------------------------------------
// Kernel 1: P = x @ W1[:64] + b1  (blocks 0..8191)  AND radius-neighbor lists
// (blocks 8192..8255; 64 blocks, 256 points each, graph pos in shared)
// ---------------------------------------------------------------------------
__global__ void prep_kernel(const float* __restrict__ x,
                            const float* __restrict__ pos,
                            const float* __restrict__ W1,
                            const float* __restrict__ b1)
{
    const int bid = blockIdx.x;
    const int tid = threadIdx.x;

    if (bid < NTOT/2) {
        // ---- P part: 2 rows per block, 128 channels each ----
        const int i = bid*2 + (tid >> 7);
        const int k = tid & 127;
        const float* xr = x + i*FIN;
        float acc = __ldg(&b1[k]);
        #pragma unroll
        for (int t = 0; t < FIN; t++)
            acc += __ldg(&xr[t]) * __ldg(&W1[t*H1D + k]);
        g_P[i*H1D + k] = acc;
    } else {
        // ---- neighbor part ----
        const int nb   = bid - NTOT/2;     // 0..63
        const int b    = nb >> 3;          // graph id
        const int base = b * NPTS;
        __shared__ float sx[NPTS], sy[NPTS], sz[NPTS];
        for (int t = tid; t < NPTS; t += 256) {
            sx[t] = pos[(base+t)*3 + 0];
            sy[t] = pos[(base+t)*3 + 1];
            sz[t] = pos[(base+t)*3 + 2];
        }
        __syncthreads();

        const int li = (nb & 7)*256 + tid;      // local point index in graph
        const float px = sx[li], py = sy[li], pz = sz[li];

        float nd[KNB]; int nj[KNB]; int cnt = 0;
        for (int j = 0; j < NPTS; j++) {
            float dx = sx[j]-px, dy = sy[j]-py, dz = sz[j]-pz;
            float d2 = dx*dx + dy*dy + dz*dz;
            if (d2 <= R2V && j != li) {
                if (cnt < KNB) {
                    nd[cnt] = d2; nj[cnt] = j; cnt++;
                } else {
                    // rare: >32 within radius -> keep 32 smallest (matches top_k+mask)
                    int mx = 0; float mv = nd[0];
                    for (int s = 1; s < KNB; s++)
                        if (nd[s] > mv) { mv = nd[s]; mx = s; }
                    if (d2 < mv) { nd[mx] = d2; nj[mx] = j; }
                }
            }
        }
        const int gi = base + li;
        g_cnt[gi] = cnt;
        for (int s = 0; s < cnt; s++) g_nbr[gi*KNB + s] = base + nj[s];
    }
}

// ---------------------------------------------------------------------------
// Kernel 2: blocks 0..7 run FPS (one graph each); blocks 8.. run the edge MLP
// (16 points per block) with max-aggregation.  FPS overlaps "for free".
// ---------------------------------------------------------------------------
__global__ void main_kernel(const float* __restrict__ pos,
                            const float* __restrict__ W1,
                            const float* __restrict__ W2,
                            const float* __restrict__ b2)
{
    __shared__ __align__(16) float smem[6208];
    const int bid = blockIdx.x;
    const int tid = threadIdx.x;

    if (bid < BGR) {
        // =========== FPS on graph `bid` ===========
        float* sx = smem;
        float* sy = smem + 2048;
        float* sz = smem + 4096;
        float* rv = smem + 6144;               // 8 warp bests
        int*   ri = (int*)(smem + 6152);
        int*   sl = (int*)(smem + 6160);

        const int base = bid * NPTS;
        for (int t = tid; t < NPTS; t += 256) {
            sx[t] = pos[(base+t)*3 + 0];
            sy[t] = pos[(base+t)*3 + 1];
            sz[t] = pos[(base+t)*3 + 2];
        }
        float mind[8];
        #pragma unroll
        for (int t = 0; t < 8; t++) mind[t] = 3.4e38f;
        if (tid == 0) g_fps[bid*MS] = 0;
        __syncthreads();

        int last = 0;
        for (int s = 1; s < MS; s++) {
            const float lx = sx[last], ly = sy[last], lz = sz[last];
            float bv = -1.0f; int bi = 0;
            #pragma unroll
            for (int t = 0; t < 8; t++) {
                const int p = t*256 + tid;
                float dx = sx[p]-lx, dy = sy[p]-ly, dz = sz[p]-lz;
                float d  = dx*dx + dy*dy + dz*dz;
                float m  = fminf(mind[t], d);
                mind[t]  = m;
                if (m > bv) { bv = m; bi = p; }   // ascending p: ties -> smaller idx
            }
            // warp argmax (tie -> smaller index, matches jnp.argmax)
            #pragma unroll
            for (int o = 16; o > 0; o >>= 1) {
                float ov = __shfl_down_sync(0xffffffffu, bv, o);
                int   oi = __shfl_down_sync(0xffffffffu, bi, o);
                if (ov > bv || (ov == bv && oi < bi)) { bv = ov; bi = oi; }
            }
            if ((tid & 31) == 0) { rv[tid>>5] = bv; ri[tid>>5] = bi; }
            __syncthreads();
            if (tid == 0) {
                float fbv = rv[0]; int fbi = ri[0];
                for (int w = 1; w < 8; w++)
                    if (rv[w] > fbv || (rv[w] == fbv && ri[w] < fbi)) { fbv = rv[w]; fbi = ri[w]; }
                sl[0] = fbi;
                g_fps[bid*MS + s] = fbi;
            }
            __syncthreads();
            last = sl[0];
        }
    } else {
        // =========== edge MLP + max aggregation, 16 points ===========
        float* sh1 = smem;                     // up to 32 edges x 128 (relu'd h1)
        const int   i0  = (bid - BGR) * 16;
        const float b2c = __ldg(&b2[tid]);     // this thread's output channel bias
        const float* w1p = W1 + FIN*H1D;       // W1 rows 64..66 (pos part)

        for (int pi = 0; pi < 16; pi++) {
            const int i   = i0 + pi;
            const int cnt = g_cnt[i];
            const float px = __ldg(&pos[i*3+0]);
            const float py = __ldg(&pos[i*3+1]);
            const float pz = __ldg(&pos[i*3+2]);

            // stage h1 for all valid edges of point i
            for (int idx = tid; idx < cnt*H1D; idx += 256) {
                const int e = idx >> 7, k = idx & 127;
                const int j = g_nbr[i*KNB + e];
                const float rx = __ldg(&pos[j*3+0]) - px;
                const float ry = __ldg(&pos[j*3+1]) - py;
                const float rz = __ldg(&pos[j*3+2]) - pz;
                float h = g_P[j*H1D + k]
                        + rx*__ldg(&w1p[k])
                        + ry*__ldg(&w1p[H1D + k])
                        + rz*__ldg(&w1p[2*H1D + k]);
                sh1[idx] = fmaxf(h, 0.0f);
            }
            __syncthreads();

            // layer 2: z = h1 @ W2 + b2, relu, max over edges
            float m = -3.4e38f;
            const float4* sh1v = (const float4*)sh1;
            for (int g = 0; g < cnt; g += 4) {
                float z0 = b2c, z1 = b2c, z2 = b2c, z3 = b2c;
                const int r0 = g * 32;         // float4 row stride = 128/4
                #pragma unroll 8
                for (int k = 0; k < H1D; k += 4) {
                    const int kq = k >> 2;
                    const float4 a0 = sh1v[r0      + kq];
                    const float4 a1 = sh1v[r0 + 32 + kq];
                    const float4 a2 = sh1v[r0 + 64 + kq];
                    const float4 a3 = sh1v[r0 + 96 + kq];
                    const float w0 = __ldg(&W2[(k+0)*H2D + tid]);
                    const float w1 = __ldg(&W2[(k+1)*H2D + tid]);
                    const float w2 = __ldg(&W2[(k+2)*H2D + tid]);
                    const float w3 = __ldg(&W2[(k+3)*H2D + tid]);
                    z0 += a0.x*w0 + a0.y*w1 + a0.z*w2 + a0.w*w3;
                    z1 += a1.x*w0 + a1.y*w1 + a1.z*w2 + a1.w*w3;
                    z2 += a2.x*w0 + a2.y*w1 + a2.z*w2 + a2.w*w3;
                    z3 += a3.x*w0 + a3.y*w1 + a3.z*w2 + a3.w*w3;
                }
                m = fmaxf(m, fmaxf(z0, 0.0f));
                if (g+1 < cnt) m = fmaxf(m, fmaxf(z1, 0.0f));
                if (g+2 < cnt) m = fmaxf(m, fmaxf(z2, 0.0f));
                if (g+3 < cnt) m = fmaxf(m, fmaxf(z3, 0.0f));
            }
            g_agg[i*H2D + tid] = (cnt > 0) ? m : 0.0f;   // PyG zero-fill for isolated nodes
            __syncthreads();
        }
    }
}

// ---------------------------------------------------------------------------
// Kernel 3: out = g_agg @ Wg + bg   (64x64 tile, 4x4 per thread)
// writes x_all into d_out[0 : 16384*256]
// ---------------------------------------------------------------------------
__global__ void gemm_kernel(const float* __restrict__ Wg,
                            const float* __restrict__ bgv,
                            float* __restrict__ out)
{
    __shared__ __align__(16) float As[16][68];
    __shared__ __align__(16) float Bs[16][68];
    const int tid = threadIdx.x;
    const int rb  = blockIdx.x * 64;
    const int cb  = blockIdx.y * 64;
    const int ty  = tid >> 4, tx = tid & 15;

    float acc[4][4];
    #pragma unroll
    for (int r = 0; r < 4; r++)
        #pragma unroll
        for (int c = 0; c < 4; c++) acc[r][c] = 0.0f;

    for (int k0 = 0; k0 < H2D; k0 += 16) {
        {   // load A tile (64 rows x 16 k), store k-major
            const int r  = tid >> 2;
            const int kq = (tid & 3) * 4;
            float4 v = *(const float4*)&g_agg[(rb+r)*H2D + k0 + kq];
            As[kq+0][r] = v.x; As[kq+1][r] = v.y; As[kq+2][r] = v.z; As[kq+3][r] = v.w;
        }
        {   // load B tile (16 k x 64 cols)
            const int k = tid >> 4;
            const int c = (tid & 15) * 4;
            *(float4*)&Bs[k][c] = *(const float4*)&Wg[(k0+k)*GOUTD + cb + c];
        }
        __syncthreads();
        #pragma unroll
        for (int k = 0; k < 16; k++) {
            const float4 a = *(const float4*)&As[k][ty*4];
            const float4 b = *(const float4*)&Bs[k][tx*4];
            acc[0][0] += a.x*b.x; acc[0][1] += a.x*b.y; acc[0][2] += a.x*b.z; acc[0][3] += a.x*b.w;
            acc[1][0] += a.y*b.x; acc[1][1] += a.y*b.y; acc[1][2] += a.y*b.z; acc[1][3] += a.y*b.w;
            acc[2][0] += a.z*b.x; acc[2][1] += a.z*b.y; acc[2][2] += a.z*b.z; acc[2][3] += a.z*b.w;
            acc[3][0] += a.w*b.x; acc[3][1] += a.w*b.y; acc[3][2] += a.w*b.z; acc[3][3] += a.w*b.w;
        }
        __syncthreads();
    }
    #pragma unroll
    for (int r = 0; r < 4; r++) {
        const int row = rb + ty*4 + r;
        #pragma unroll
        for (int c = 0; c < 4; c++) {
            const int col = cb + tx*4 + c;
            out[row*GOUTD + col] = acc[r][c] + __ldg(&bgv[col]);
        }
    }
}

// ---------------------------------------------------------------------------
// Kernel 4: gather x_dst / pos_dst / batch_dst from fps indices
// ---------------------------------------------------------------------------
__global__ void gather_kernel(const float* __restrict__ pos,
                              float* __restrict__ out)
{
    const int s   = blockIdx.x;          // 0..4095 dst rows
    const int tid = threadIdx.x;         // 256
    const int b   = s >> 9;
    const int m   = s & 511;
    const int gi  = b*NPTS + g_fps[b*MS + m];

    const float* x_all = out;
    float* xd = out + NTOT*GOUTD;                  // x_dst   [4096,256]
    float* pd = xd  + BGR*MS*GOUTD;                // pos_dst [4096,3]
    float* bd = pd  + BGR*MS*3;                    // batch_dst [4096]

    xd[s*GOUTD + tid] = x_all[gi*GOUTD + tid];
    if (tid < 3)  pd[s*3 + tid] = pos[gi*3 + tid];
    if (tid == 3) bd[s] = (float)b;
}

// ---------------------------------------------------------------------------
extern "C" void kernel_launch(void* const* d_in, const int* in_sizes, int n_in,
                              void* d_out, int out_size)
{
    (void)in_sizes; (void)n_in; (void)out_size;
    const float* x   = (const float*)d_in[0];
    const float* pos = (const float*)d_in[1];
    // d_in[2] = batch (int32), derivable -> unused
    const float* W1  = (const float*)d_in[3];
    const float* b1  = (const float*)d_in[4];
    const float* W2  = (const float*)d_in[5];
    const float* b2  = (const float*)d_in[6];
    const float* Wg  = (const float*)d_in[7];
    const float* bg  = (const float*)d_in[8];
    float* out = (float*)d_out;

    prep_kernel<<<NTOT/2 + 64, 256>>>(x, pos, W1, b1);
    main_kernel<<<BGR + NTOT/16, 256>>>(pos, W1, W2, b2);
    gemm_kernel<<<dim3(NTOT/64, GOUTD/64), 256>>>(Wg, bg, out);
    gather_kernel<<<BGR*MS, 256>>>(pos, out);
}

// round 5
// speedup vs baseline: 1.3862x; 1.3862x over previous
#include <cuda_runtime.h>

// Problem constants
#define BGR   8
#define NPTS  2048
#define NTOT  (BGR*NPTS)      // 16384
#define FIN   64
#define KNB   32
#define MS    512             // fps samples per graph
#define H1D   128
#define H2D   256
#define GOUTD 256
#define R2V   0.01f
#define GMAX  (NTOT*2)        // max padded groups (cnt<=32 -> <=2 groups/pt)

// Scratch (static device globals — no runtime allocation)
__device__ float g_P[NTOT*H1D];     // x @ W1[:64] + b1
__device__ int   g_nbr[NTOT*KNB];   // global neighbor indices
__device__ int   g_cnt[NTOT];       // valid neighbor count (<=32)
__device__ float g_agg[NTOT*H2D];   // max-aggregated features
__device__ int   g_fps[BGR*MS];     // local fps indices per graph
__device__ int   g_grp_pt[GMAX];    // group -> point
__device__ int   g_grp_q[GMAX];     // group -> group index within point
__device__ int   g_G;               // number of groups

// ---------------------------------------------------------------------------
// tf32 helpers
// ---------------------------------------------------------------------------
__device__ __forceinline__ unsigned f2tf32(float f) {
    unsigned r;
    asm("cvt.rna.tf32.f32 %0, %1;" : "=r"(r) : "f"(f));
    return r;
}

__device__ __forceinline__ void mma_tf32(float* c, const unsigned* a, const unsigned* b) {
    asm volatile(
        "mma.sync.aligned.m16n8k8.row.col.f32.tf32.tf32.f32 "
        "{%0,%1,%2,%3}, {%4,%5,%6,%7}, {%8,%9}, {%0,%1,%2,%3};"
        : "+f"(c[0]), "+f"(c[1]), "+f"(c[2]), "+f"(c[3])
        : "r"(a[0]), "r"(a[1]), "r"(a[2]), "r"(a[3]), "r"(b[0]), "r"(b[1]));
}

// ---------------------------------------------------------------------------
// Kernel 1: P = x @ W1[:64] + b1 (blocks 0..8191), radius neighbor lists
// (blocks 8192..8255), zero g_agg (blocks 8256..9279)
// ---------------------------------------------------------------------------
__global__ __launch_bounds__(256)
void prep_kernel(const float* __restrict__ x,
                 const float* __restrict__ pos,
                 const float* __restrict__ W1,
                 const float* __restrict__ b1)
{
    const int bid = blockIdx.x;
    const int tid = threadIdx.x;

    if (bid < NTOT/2) {
        // ---- P part: 2 rows per block, 128 channels each ----
        const int i = bid*2 + (tid >> 7);
        const int k = tid & 127;
        const float* xr = x + i*FIN;
        float acc = __ldg(&b1[k]);
        #pragma unroll
        for (int t = 0; t < FIN; t++)
            acc += __ldg(&xr[t]) * __ldg(&W1[t*H1D + k]);
        g_P[i*H1D + k] = acc;
    } else if (bid < NTOT/2 + 64) {
        // ---- neighbor part ----
        const int nb   = bid - NTOT/2;     // 0..63
        const int b    = nb >> 3;          // graph id
        const int base = b * NPTS;
        __shared__ float sx[NPTS], sy[NPTS], sz[NPTS];
        for (int t = tid; t < NPTS; t += 256) {
            sx[t] = pos[(base+t)*3 + 0];
            sy[t] = pos[(base+t)*3 + 1];
            sz[t] = pos[(base+t)*3 + 2];
        }
        __syncthreads();

        const int li = (nb & 7)*256 + tid;
        const float px = sx[li], py = sy[li], pz = sz[li];

        float nd[KNB]; int nj[KNB]; int cnt = 0;
        for (int j = 0; j < NPTS; j++) {
            float dx = sx[j]-px, dy = sy[j]-py, dz = sz[j]-pz;
            float d2 = dx*dx + dy*dy + dz*dz;
            if (d2 <= R2V && j != li) {
                if (cnt < KNB) {
                    nd[cnt] = d2; nj[cnt] = j; cnt++;
                } else {
                    int mx = 0; float mv = nd[0];
                    for (int s = 1; s < KNB; s++)
                        if (nd[s] > mv) { mv = nd[s]; mx = s; }
                    if (d2 < mv) { nd[mx] = d2; nj[mx] = j; }
                }
            }
        }
        const int gi = base + li;
        g_cnt[gi] = cnt;
        for (int s = 0; s < cnt; s++) g_nbr[gi*KNB + s] = base + nj[s];
    } else {
        // ---- zero g_agg: 1024 blocks, 4096 floats each ----
        const int zb = bid - (NTOT/2 + 64);
        float4* p = reinterpret_cast<float4*>(g_agg);
        const float4 z = make_float4(0.f, 0.f, 0.f, 0.f);
        #pragma unroll
        for (int t = 0; t < 4; t++)
            p[zb*1024 + t*256 + tid] = z;
    }
}

// ---------------------------------------------------------------------------
// Kernel 2: build padded group list via block-wide prefix sum (1 block, 1024 thr)
// __launch_bounds__(1024) is REQUIRED: without it ptxas assigned >64 regs and
// the 1024-thread launch failed with "too many resources requested".
// ---------------------------------------------------------------------------
__global__ __launch_bounds__(1024)
void scan_kernel()
{
    __shared__ int wsum[32];
    const int tid  = threadIdx.x;
    const int base = tid * 16;

    // per-thread total group count (recompute ng later; keeps regs low)
    int s = 0;
    #pragma unroll
    for (int t = 0; t < 16; t++)
        s += (g_cnt[base + t] + 15) >> 4;

    // warp inclusive scan of s
    int v = s;
    #pragma unroll
    for (int o = 1; o < 32; o <<= 1) {
        int u = __shfl_up_sync(0xffffffffu, v, o);
        if ((tid & 31) >= o) v += u;
    }
    if ((tid & 31) == 31) wsum[tid >> 5] = v;
    __syncthreads();
    if (tid < 32) {
        int w = wsum[tid];
        int vv = w;
        #pragma unroll
        for (int o = 1; o < 32; o <<= 1) {
            int u = __shfl_up_sync(0xffffffffu, vv, o);
            if (tid >= o) vv += u;
        }
        wsum[tid] = vv - w;              // exclusive warp offsets
    }
    __syncthreads();
    int go = wsum[tid >> 5] + (v - s);   // exclusive prefix for this thread

    for (int t = 0; t < 16; t++) {
        const int n = (g_cnt[base + t] + 15) >> 4;
        for (int q = 0; q < n; q++) {
            g_grp_pt[go + q] = base + t;
            g_grp_q [go + q] = q;
        }
        go += n;
    }
    if (tid == 1023) g_G = go;
}

// ---------------------------------------------------------------------------
// Kernel 3: blocks 0..7 = FPS; blocks 8.. = tf32 MMA edge GEMM + max-agg.
// Per GEMM block: 8 groups (128 rows) x 128 cols, K=128 (one shot).
// Shared layout (u32 units): aF[16384] | bF[16384] | sJ[128] | sRx/sRy/sRz[128]
//                            | sW1[384] | sPt[8]
// ---------------------------------------------------------------------------
#define AF_OFF 0
#define BF_OFF 16384
#define SJ_OFF 32768
#define RX_OFF 32896
#define RY_OFF 33024
#define RZ_OFF 33152
#define SW_OFF 33280
#define PT_OFF 33664
#define EDGE_SMEM_BYTES (33672*4)

extern __shared__ __align__(16) unsigned dsm[];

__global__ __launch_bounds__(256, 1)
void edge_kernel(const float* __restrict__ pos,
                 const float* __restrict__ W1,
                 const float* __restrict__ W2,
                 const float* __restrict__ b2)
{
    const int bid = blockIdx.x;
    const int tid = threadIdx.x;

    if (bid < BGR) {
        // =========== FPS on graph `bid` (validated in prior rounds) ===========
        float* smemf = (float*)dsm;
        float* sx = smemf;
        float* sy = smemf + 2048;
        float* sz = smemf + 4096;
        float* rv = smemf + 6144;
        int*   ri = (int*)(smemf + 6152);
        int*   sl = (int*)(smemf + 6160);

        const int base = bid * NPTS;
        for (int t = tid; t < NPTS; t += 256) {
            sx[t] = pos[(base+t)*3 + 0];
            sy[t] = pos[(base+t)*3 + 1];
            sz[t] = pos[(base+t)*3 + 2];
        }
        float mind[8];
        #pragma unroll
        for (int t = 0; t < 8; t++) mind[t] = 3.4e38f;
        if (tid == 0) g_fps[bid*MS] = 0;
        __syncthreads();

        int last = 0;
        for (int s = 1; s < MS; s++) {
            const float lx = sx[last], ly = sy[last], lz = sz[last];
            float bv = -1.0f; int bi = 0;
            #pragma unroll
            for (int t = 0; t < 8; t++) {
                const int p = t*256 + tid;
                float dx = sx[p]-lx, dy = sy[p]-ly, dz = sz[p]-lz;
                float d  = dx*dx + dy*dy + dz*dz;
                float m  = fminf(mind[t], d);
                mind[t]  = m;
                if (m > bv) { bv = m; bi = p; }
            }
            #pragma unroll
            for (int o = 16; o > 0; o >>= 1) {
                float ov = __shfl_down_sync(0xffffffffu, bv, o);
                int   oi = __shfl_down_sync(0xffffffffu, bi, o);
                if (ov > bv || (ov == bv && oi < bi)) { bv = ov; bi = oi; }
            }
            if ((tid & 31) == 0) { rv[tid>>5] = bv; ri[tid>>5] = bi; }
            __syncthreads();
            if (tid == 0) {
                float fbv = rv[0]; int fbi = ri[0];
                for (int w = 1; w < 8; w++)
                    if (rv[w] > fbv || (rv[w] == fbv && ri[w] < fbi)) { fbv = rv[w]; fbi = ri[w]; }
                sl[0] = fbi;
                g_fps[bid*MS + s] = fbi;
            }
            __syncthreads();
            last = sl[0];
        }
        return;
    }

    // =========== tf32 MMA edge GEMM ===========
    const int G   = g_G;
    const int gb  = bid - BGR;
    const int g0  = (gb >> 1) * 8;           // first group of this M-tile
    const int cb  = (gb & 1) * 128;          // N-tile col base
    if (g0 >= G) return;

    uint4* aF  = reinterpret_cast<uint4*>(dsm + AF_OFF);
    uint2* bF  = reinterpret_cast<uint2*>(dsm + BF_OFF);
    int*   sJ  = reinterpret_cast<int*>  (dsm + SJ_OFF);
    float* sRx = reinterpret_cast<float*>(dsm + RX_OFF);
    float* sRy = reinterpret_cast<float*>(dsm + RY_OFF);
    float* sRz = reinterpret_cast<float*>(dsm + RZ_OFF);
    float* sW1 = reinterpret_cast<float*>(dsm + SW_OFF);
    int*   sPt = reinterpret_cast<int*>  (dsm + PT_OFF);

    // ---- stage per-row metadata (128 rows) and W1 pos-rows ----
    if (tid < 128) {
        const int mt = tid >> 4, rl = tid & 15;
        const int g  = g0 + mt;
        int j = 0; float rx = 0.f, ry = 0.f, rz = 0.f; int pt = -1;
        if (g < G) {
            pt = g_grp_pt[g];
            const int q   = g_grp_q[g];
            const int cnt = g_cnt[pt];
            int s = q*16 + rl;
            if (s >= cnt) s = q*16;          // pad rows duplicate group's first edge
            j  = g_nbr[pt*KNB + s];
            rx = __ldg(&pos[j*3+0]) - __ldg(&pos[pt*3+0]);
            ry = __ldg(&pos[j*3+1]) - __ldg(&pos[pt*3+1]);
            rz = __ldg(&pos[j*3+2]) - __ldg(&pos[pt*3+2]);
        }
        sJ[tid] = j; sRx[tid] = rx; sRy[tid] = ry; sRz[tid] = rz;
        if (rl == 0) sPt[mt] = pt;
    }
    for (int t = tid; t < 384; t += 256) sW1[t] = __ldg(&W1[FIN*H1D + t]);
    __syncthreads();

    // ---- build A fragments (h1, fragment-major): 4096 uint4, 16/thread ----
    #pragma unroll
    for (int it = 0; it < 16; it++) {
        const int flat = it*256 + tid;       // (mt*16 + ks)*32 + lane
        const int lane = flat & 31;
        const int ks   = (flat >> 5) & 15;
        const int mt   = flat >> 9;
        const int r0   = mt*16 + (lane >> 2);
        const int r1   = r0 + 8;
        const int k0   = ks*8 + (lane & 3);
        const int k1   = k0 + 4;
        const int j0 = sJ[r0], j1 = sJ[r1];
        const float w0a = sW1[k0], w0b = sW1[128+k0], w0c = sW1[256+k0];
        const float w1a = sW1[k1], w1b = sW1[128+k1], w1c = sW1[256+k1];
        float h00 = g_P[j0*H1D + k0] + sRx[r0]*w0a + sRy[r0]*w0b + sRz[r0]*w0c;
        float h10 = g_P[j1*H1D + k0] + sRx[r1]*w0a + sRy[r1]*w0b + sRz[r1]*w0c;
        float h01 = g_P[j0*H1D + k1] + sRx[r0]*w1a + sRy[r0]*w1b + sRz[r0]*w1c;
        float h11 = g_P[j1*H1D + k1] + sRx[r1]*w1a + sRy[r1]*w1b + sRz[r1]*w1c;
        uint4 v;
        v.x = f2tf32(fmaxf(h00, 0.f));
        v.y = f2tf32(fmaxf(h10, 0.f));
        v.z = f2tf32(fmaxf(h01, 0.f));
        v.w = f2tf32(fmaxf(h11, 0.f));
        aF[flat] = v;
    }

    // ---- build B fragments (W2 tile, fragment-major): 8192 uint2, 32/thread ----
    #pragma unroll
    for (int it = 0; it < 32; it++) {
        const int flat = it*256 + tid;       // (nt*16 + ks)*32 + lane
        const int lane = flat & 31;
        const int ks   = (flat >> 5) & 15;
        const int nt   = flat >> 9;
        const int k0   = ks*8 + (lane & 3);
        const int col  = cb + nt*8 + (lane >> 2);
        uint2 v;
        v.x = f2tf32(__ldg(&W2[k0*H2D + col]));
        v.y = f2tf32(__ldg(&W2[(k0+4)*H2D + col]));
        bF[flat] = v;
    }
    __syncthreads();

    // ---- mainloop: warps 4x2 (warp = 32 rows x 64 cols) ----
    const int warp = tid >> 5, lane = tid & 31;
    const int wm = warp & 3, wn = warp >> 2;
    const int mt0 = wm*2, mt1 = wm*2 + 1;

    float acc[2][8][4];
    #pragma unroll
    for (int a = 0; a < 2; a++)
        #pragma unroll
        for (int n = 0; n < 8; n++)
            #pragma unroll
            for (int r = 0; r < 4; r++) acc[a][n][r] = 0.f;

    #pragma unroll
    for (int ks = 0; ks < 16; ks++) {
        uint4 a0 = aF[(mt0*16 + ks)*32 + lane];
        uint4 a1 = aF[(mt1*16 + ks)*32 + lane];
        #pragma unroll
        for (int nt = 0; nt < 8; nt++) {
            uint2 b = bF[((wn*8 + nt)*16 + ks)*32 + lane];
            mma_tf32(acc[0][nt], &a0.x, &b.x);
            mma_tf32(acc[1][nt], &a1.x, &b.x);
        }
    }

    // ---- epilogue: +b2, relu, max over the 16 rows of each group, atomicMax ----
    #pragma unroll
    for (int lm = 0; lm < 2; lm++) {
        const int g = g0 + wm*2 + lm;
        if (g >= G) continue;
        const int pt = sPt[wm*2 + lm];
        #pragma unroll
        for (int nt = 0; nt < 8; nt++) {
            float p0 = fmaxf(acc[lm][nt][0], acc[lm][nt][2]);   // rows r', r'+8
            float p1 = fmaxf(acc[lm][nt][1], acc[lm][nt][3]);
            #pragma unroll
            for (int o = 4; o < 32; o <<= 1) {                  // reduce across t/4
                p0 = fmaxf(p0, __shfl_xor_sync(0xffffffffu, p0, o));
                p1 = fmaxf(p1, __shfl_xor_sync(0xffffffffu, p1, o));
            }
            if (lane < 4) {
                const int col = cb + (wn*8 + nt)*8 + 2*lane;
                const float m0 = fmaxf(p0 + __ldg(&b2[col]),     0.f);
                const float m1 = fmaxf(p1 + __ldg(&b2[col + 1]), 0.f);
                atomicMax((int*)&g_agg[pt*H2D + col],     __float_as_int(m0));
                atomicMax((int*)&g_agg[pt*H2D + col + 1], __float_as_int(m1));
            }
        }
    }
}

// ---------------------------------------------------------------------------
// Kernel 4: out = g_agg @ Wg + bg  (exact fp32 scalar)
// ---------------------------------------------------------------------------
__global__ __launch_bounds__(256)
void gemm_kernel(const float* __restrict__ Wg,
                 const float* __restrict__ bgv,
                 float* __restrict__ out)
{
    __shared__ __align__(16) float As[16][68];
    __shared__ __align__(16) float Bs[16][68];
    const int tid = threadIdx.x;
    const int rb  = blockIdx.x * 64;
    const int cb  = blockIdx.y * 64;
    const int ty  = tid >> 4, tx = tid & 15;

    float acc[4][4];
    #pragma unroll
    for (int r = 0; r < 4; r++)
        #pragma unroll
        for (int c = 0; c < 4; c++) acc[r][c] = 0.0f;

    for (int k0 = 0; k0 < H2D; k0 += 16) {
        {
            const int r  = tid >> 2;
            const int kq = (tid & 3) * 4;
            float4 v = *(const float4*)&g_agg[(rb+r)*H2D + k0 + kq];
            As[kq+0][r] = v.x; As[kq+1][r] = v.y; As[kq+2][r] = v.z; As[kq+3][r] = v.w;
        }
        {
            const int k = tid >> 4;
            const int c = (tid & 15) * 4;
            *(float4*)&Bs[k][c] = *(const float4*)&Wg[(k0+k)*GOUTD + cb + c];
        }
        __syncthreads();
        #pragma unroll
        for (int k = 0; k < 16; k++) {
            const float4 a = *(const float4*)&As[k][ty*4];
            const float4 b = *(const float4*)&Bs[k][tx*4];
            acc[0][0] += a.x*b.x; acc[0][1] += a.x*b.y; acc[0][2] += a.x*b.z; acc[0][3] += a.x*b.w;
            acc[1][0] += a.y*b.x; acc[1][1] += a.y*b.y; acc[1][2] += a.y*b.z; acc[1][3] += a.y*b.w;
            acc[2][0] += a.z*b.x; acc[2][1] += a.z*b.y; acc[2][2] += a.z*b.z; acc[2][3] += a.z*b.w;
            acc[3][0] += a.w*b.x; acc[3][1] += a.w*b.y; acc[3][2] += a.w*b.z; acc[3][3] += a.w*b.w;
        }
        __syncthreads();
    }
    #pragma unroll
    for (int r = 0; r < 4; r++) {
        const int row = rb + ty*4 + r;
        #pragma unroll
        for (int c = 0; c < 4; c++) {
            const int col = cb + tx*4 + c;
            out[row*GOUTD + col] = acc[r][c] + __ldg(&bgv[col]);
        }
    }
}

// ---------------------------------------------------------------------------
// Kernel 5: gather x_dst / pos_dst / batch_dst from fps indices
// ---------------------------------------------------------------------------
__global__ __launch_bounds__(256)
void gather_kernel(const float* __restrict__ pos,
                   float* __restrict__ out)
{
    const int s   = blockIdx.x;
    const int tid = threadIdx.x;
    const int b   = s >> 9;
    const int m   = s & 511;
    const int gi  = b*NPTS + g_fps[b*MS + m];

    const float* x_all = out;
    float* xd = out + NTOT*GOUTD;
    float* pd = xd  + BGR*MS*GOUTD;
    float* bd = pd  + BGR*MS*3;

    xd[s*GOUTD + tid] = x_all[gi*GOUTD + tid];
    if (tid < 3)  pd[s*3 + tid] = pos[gi*3 + tid];
    if (tid == 3) bd[s] = (float)b;
}

// ---------------------------------------------------------------------------
extern "C" void kernel_launch(void* const* d_in, const int* in_sizes, int n_in,
                              void* d_out, int out_size)
{
    (void)in_sizes; (void)n_in; (void)out_size;
    const float* x   = (const float*)d_in[0];
    const float* pos = (const float*)d_in[1];
    const float* W1  = (const float*)d_in[3];
    const float* b1  = (const float*)d_in[4];
    const float* W2  = (const float*)d_in[5];
    const float* b2  = (const float*)d_in[6];
    const float* Wg  = (const float*)d_in[7];
    const float* bg  = (const float*)d_in[8];
    float* out = (float*)d_out;

    static int smem_set = 0;
    if (!smem_set) {
        cudaFuncSetAttribute(edge_kernel,
                             cudaFuncAttributeMaxDynamicSharedMemorySize,
                             EDGE_SMEM_BYTES);
        smem_set = 1;
    }

    prep_kernel<<<NTOT/2 + 64 + 1024, 256>>>(x, pos, W1, b1);
    scan_kernel<<<1, 1024>>>();
    edge_kernel<<<BGR + (GMAX/8)*2, 256, EDGE_SMEM_BYTES>>>(pos, W1, W2, b2);
    gemm_kernel<<<dim3(NTOT/64, GOUTD/64), 256>>>(Wg, bg, out);
    gather_kernel<<<BGR*MS, 256>>>(pos, out);
}

// round 6
// speedup vs baseline: 1.7858x; 1.2883x over previous
#include <cuda_runtime.h>
#include <cuda_fp16.h>

// Problem constants
#define BGR   8
#define NPTS  2048
#define NTOT  (BGR*NPTS)      // 16384
#define FIN   64
#define KNB   32
#define MS    512             // fps samples per graph
#define H1D   128
#define H2D   256
#define GOUTD 256
#define R2V   0.01f
#define GMAX  (NTOT*2)        // max padded groups (cnt<=32 -> <=2 groups/pt)

// Scratch (static device globals — no runtime allocation)
__device__ float g_P[NTOT*H1D];     // x @ W1[:64] + b1
__device__ int   g_nbr[NTOT*KNB];   // global neighbor indices
__device__ int   g_cnt[NTOT];       // valid neighbor count (<=32)
__device__ float g_agg[NTOT*H2D];   // max-aggregated features
__device__ int   g_fps[BGR*MS];     // local fps indices per graph
__device__ int   g_grp_pt[GMAX];    // group -> point
__device__ int   g_grp_q[GMAX];     // group -> group index within point
__device__ int   g_G;               // number of groups

// ---------------------------------------------------------------------------
// fp16 helpers
// ---------------------------------------------------------------------------
__device__ __forceinline__ unsigned pk2(float a, float b) {
    __half2 h = __floats2half2_rn(a, b);      // .x = a (low), .y = b (high)
    return *reinterpret_cast<unsigned*>(&h);
}

__device__ __forceinline__ void mma_f16(float* c, const unsigned* a, const unsigned* b) {
    asm volatile(
        "mma.sync.aligned.m16n8k16.row.col.f32.f16.f16.f32 "
        "{%0,%1,%2,%3}, {%4,%5,%6,%7}, {%8,%9}, {%0,%1,%2,%3};"
        : "+f"(c[0]), "+f"(c[1]), "+f"(c[2]), "+f"(c[3])
        : "r"(a[0]), "r"(a[1]), "r"(a[2]), "r"(a[3]), "r"(b[0]), "r"(b[1]));
}

extern __shared__ __align__(16) unsigned dsm[];

// ---------------------------------------------------------------------------
// Kernel 1: P = x @ W1[:64] + b1 (blocks 0..8191), radius neighbor lists
// (blocks 8192..8255), zero g_agg (blocks 8256..9279)
// ---------------------------------------------------------------------------
__global__ __launch_bounds__(256)
void prep_kernel(const float* __restrict__ x,
                 const float* __restrict__ pos,
                 const float* __restrict__ W1,
                 const float* __restrict__ b1)
{
    const int bid = blockIdx.x;
    const int tid = threadIdx.x;

    if (bid < NTOT/2) {
        const int i = bid*2 + (tid >> 7);
        const int k = tid & 127;
        const float* xr = x + i*FIN;
        float acc = __ldg(&b1[k]);
        #pragma unroll
        for (int t = 0; t < FIN; t++)
            acc += __ldg(&xr[t]) * __ldg(&W1[t*H1D + k]);
        g_P[i*H1D + k] = acc;
    } else if (bid < NTOT/2 + 64) {
        const int nb   = bid - NTOT/2;
        const int b    = nb >> 3;
        const int base = b * NPTS;
        __shared__ float sx[NPTS], sy[NPTS], sz[NPTS];
        for (int t = tid; t < NPTS; t += 256) {
            sx[t] = pos[(base+t)*3 + 0];
            sy[t] = pos[(base+t)*3 + 1];
            sz[t] = pos[(base+t)*3 + 2];
        }
        __syncthreads();

        const int li = (nb & 7)*256 + tid;
        const float px = sx[li], py = sy[li], pz = sz[li];

        float nd[KNB]; int nj[KNB]; int cnt = 0;
        for (int j = 0; j < NPTS; j++) {
            float dx = sx[j]-px, dy = sy[j]-py, dz = sz[j]-pz;
            float d2 = dx*dx + dy*dy + dz*dz;
            if (d2 <= R2V && j != li) {
                if (cnt < KNB) {
                    nd[cnt] = d2; nj[cnt] = j; cnt++;
                } else {
                    int mx = 0; float mv = nd[0];
                    for (int s = 1; s < KNB; s++)
                        if (nd[s] > mv) { mv = nd[s]; mx = s; }
                    if (d2 < mv) { nd[mx] = d2; nj[mx] = j; }
                }
            }
        }
        const int gi = base + li;
        g_cnt[gi] = cnt;
        for (int s = 0; s < cnt; s++) g_nbr[gi*KNB + s] = base + nj[s];
    } else {
        const int zb = bid - (NTOT/2 + 64);
        float4* p = reinterpret_cast<float4*>(g_agg);
        const float4 z = make_float4(0.f, 0.f, 0.f, 0.f);
        #pragma unroll
        for (int t = 0; t < 4; t++)
            p[zb*1024 + t*256 + tid] = z;
    }
}

// ---------------------------------------------------------------------------
// Kernel 2: build padded group list via block-wide prefix sum (1 block, 1024 thr)
// ---------------------------------------------------------------------------
__global__ __launch_bounds__(1024)
void scan_kernel()
{
    __shared__ int wsum[32];
    const int tid  = threadIdx.x;
    const int base = tid * 16;

    int s = 0;
    #pragma unroll
    for (int t = 0; t < 16; t++)
        s += (g_cnt[base + t] + 15) >> 4;

    int v = s;
    #pragma unroll
    for (int o = 1; o < 32; o <<= 1) {
        int u = __shfl_up_sync(0xffffffffu, v, o);
        if ((tid & 31) >= o) v += u;
    }
    if ((tid & 31) == 31) wsum[tid >> 5] = v;
    __syncthreads();
    if (tid < 32) {
        int w = wsum[tid];
        int vv = w;
        #pragma unroll
        for (int o = 1; o < 32; o <<= 1) {
            int u = __shfl_up_sync(0xffffffffu, vv, o);
            if (tid >= o) vv += u;
        }
        wsum[tid] = vv - w;
    }
    __syncthreads();
    int go = wsum[tid >> 5] + (v - s);

    for (int t = 0; t < 16; t++) {
        const int n = (g_cnt[base + t] + 15) >> 4;
        for (int q = 0; q < n; q++) {
            g_grp_pt[go + q] = base + t;
            g_grp_q [go + q] = q;
        }
        go += n;
    }
    if (tid == 1023) g_G = go;
}

// ---------------------------------------------------------------------------
// Kernel 3: blocks 0..7 = FPS; blocks 8.. = fp16 MMA edge GEMM + max-agg.
// Per GEMM block: 8 groups (128 rows) x FULL 256 cols, K=128 (one shot).
// smem (u32 units): aF uint4[2048] @0 | bF uint2[8192] @8192 | sJ @24576
//   | sRx @24704 | sRy @24832 | sRz @24960 | sW1 @25088 (384) | sPt @25472
// ---------------------------------------------------------------------------
#define E_AF 0
#define E_BF 8192
#define E_SJ 24576
#define E_RX 24704
#define E_RY 24832
#define E_RZ 24960
#define E_SW 25088
#define E_PT 25472
#define EDGE_SMEM_BYTES (25480*4)

__global__ __launch_bounds__(256, 1)
void edge_kernel(const float* __restrict__ pos,
                 const float* __restrict__ W1,
                 const float* __restrict__ W2,
                 const float* __restrict__ b2)
{
    const int bid = blockIdx.x;
    const int tid = threadIdx.x;

    if (bid < BGR) {
        // =========== FPS on graph `bid` (double-buffered reduce: 1 bar/iter) ==
        float* smemf = (float*)dsm;
        float* sx = smemf;
        float* sy = smemf + 2048;
        float* sz = smemf + 4096;
        float* rv = smemf + 6144;               // [2][8]
        int*   ri = (int*)(smemf + 6160);       // [2][8]

        const int base = bid * NPTS;
        for (int t = tid; t < NPTS; t += 256) {
            sx[t] = pos[(base+t)*3 + 0];
            sy[t] = pos[(base+t)*3 + 1];
            sz[t] = pos[(base+t)*3 + 2];
        }
        float mind[8];
        #pragma unroll
        for (int t = 0; t < 8; t++) mind[t] = 3.4e38f;
        if (tid == 0) g_fps[bid*MS] = 0;
        __syncthreads();

        int last = 0;
        for (int s = 1; s < MS; s++) {
            const int p = s & 1;
            const float lx = sx[last], ly = sy[last], lz = sz[last];
            float bv = -1.0f; int bi = 0;
            #pragma unroll
            for (int t = 0; t < 8; t++) {
                const int pp = t*256 + tid;
                float dx = sx[pp]-lx, dy = sy[pp]-ly, dz = sz[pp]-lz;
                float d  = dx*dx + dy*dy + dz*dz;
                float m  = fminf(mind[t], d);
                mind[t]  = m;
                if (m > bv) { bv = m; bi = pp; }
            }
            #pragma unroll
            for (int o = 16; o > 0; o >>= 1) {
                float ov = __shfl_down_sync(0xffffffffu, bv, o);
                int   oi = __shfl_down_sync(0xffffffffu, bi, o);
                if (ov > bv || (ov == bv && oi < bi)) { bv = ov; bi = oi; }
            }
            if ((tid & 31) == 0) { rv[p*8 + (tid>>5)] = bv; ri[p*8 + (tid>>5)] = bi; }
            __syncthreads();
            // every thread computes the same final argmax (no second barrier)
            float fbv = rv[p*8]; int fbi = ri[p*8];
            #pragma unroll
            for (int w = 1; w < 8; w++) {
                float wv = rv[p*8 + w]; int wi = ri[p*8 + w];
                if (wv > fbv || (wv == fbv && wi < fbi)) { fbv = wv; fbi = wi; }
            }
            last = fbi;
            if (tid == 0) g_fps[bid*MS + s] = fbi;
        }
        return;
    }

    // =========== fp16 MMA edge GEMM, 128 rows x 256 cols, K=128 ===========
    const int G  = g_G;
    const int g0 = (bid - BGR) * 8;          // first group of this M-tile
    if (g0 >= G) return;

    uint4* aF  = reinterpret_cast<uint4*>(dsm + E_AF);
    uint2* bF  = reinterpret_cast<uint2*>(dsm + E_BF);
    int*   sJ  = reinterpret_cast<int*>  (dsm + E_SJ);
    float* sRx = reinterpret_cast<float*>(dsm + E_RX);
    float* sRy = reinterpret_cast<float*>(dsm + E_RY);
    float* sRz = reinterpret_cast<float*>(dsm + E_RZ);
    float* sW1 = reinterpret_cast<float*>(dsm + E_SW);
    int*   sPt = reinterpret_cast<int*>  (dsm + E_PT);

    // ---- per-row metadata (128 rows) + W1 pos-rows ----
    if (tid < 128) {
        const int mt = tid >> 4, rl = tid & 15;
        const int g  = g0 + mt;
        int j = 0; float rx = 0.f, ry = 0.f, rz = 0.f; int pt = -1;
        if (g < G) {
            pt = g_grp_pt[g];
            const int q   = g_grp_q[g];
            const int cnt = g_cnt[pt];
            int s = q*16 + rl;
            if (s >= cnt) s = q*16;          // pad rows duplicate group's first edge
            j  = g_nbr[pt*KNB + s];
            rx = __ldg(&pos[j*3+0]) - __ldg(&pos[pt*3+0]);
            ry = __ldg(&pos[j*3+1]) - __ldg(&pos[pt*3+1]);
            rz = __ldg(&pos[j*3+2]) - __ldg(&pos[pt*3+2]);
        }
        sJ[tid] = j; sRx[tid] = rx; sRy[tid] = ry; sRz[tid] = rz;
        if (rl == 0) sPt[mt] = pt;
    }
    for (int t = tid; t < 384; t += 256) sW1[t] = __ldg(&W1[FIN*H1D + t]);
    __syncthreads();

    // ---- build A fragments (h1 fp16, fragment-major): 2048 uint4, 8/thread --
    #pragma unroll
    for (int it = 0; it < 8; it++) {
        const int flat = it*256 + tid;       // (mt*8 + ks)*32 + lane
        const int lane = flat & 31;
        const int ks   = (flat >> 5) & 7;
        const int mt   = flat >> 8;
        const int r0   = mt*16 + (lane >> 2);
        const int r1   = r0 + 8;
        const int k0   = ks*16 + (lane & 3)*2;
        const int j0 = sJ[r0], j1 = sJ[r1];
        const float rx0 = sRx[r0], ry0 = sRy[r0], rz0 = sRz[r0];
        const float rx1 = sRx[r1], ry1 = sRy[r1], rz1 = sRz[r1];
        const float2 p00 = *(const float2*)&g_P[j0*H1D + k0];
        const float2 p01 = *(const float2*)&g_P[j0*H1D + k0 + 8];
        const float2 p10 = *(const float2*)&g_P[j1*H1D + k0];
        const float2 p11 = *(const float2*)&g_P[j1*H1D + k0 + 8];
        const float wa0 = sW1[k0],       wa1 = sW1[k0+1],       wa8 = sW1[k0+8],       wa9 = sW1[k0+9];
        const float wb0 = sW1[128+k0],   wb1 = sW1[128+k0+1],   wb8 = sW1[128+k0+8],   wb9 = sW1[128+k0+9];
        const float wc0 = sW1[256+k0],   wc1 = sW1[256+k0+1],   wc8 = sW1[256+k0+8],   wc9 = sW1[256+k0+9];
        uint4 v;
        v.x = pk2(fmaxf(p00.x + rx0*wa0 + ry0*wb0 + rz0*wc0, 0.f),
                  fmaxf(p00.y + rx0*wa1 + ry0*wb1 + rz0*wc1, 0.f));
        v.y = pk2(fmaxf(p10.x + rx1*wa0 + ry1*wb0 + rz1*wc0, 0.f),
                  fmaxf(p10.y + rx1*wa1 + ry1*wb1 + rz1*wc1, 0.f));
        v.z = pk2(fmaxf(p01.x + rx0*wa8 + ry0*wb8 + rz0*wc8, 0.f),
                  fmaxf(p01.y + rx0*wa9 + ry0*wb9 + rz0*wc9, 0.f));
        v.w = pk2(fmaxf(p11.x + rx1*wa8 + ry1*wb8 + rz1*wc8, 0.f),
                  fmaxf(p11.y + rx1*wa9 + ry1*wb9 + rz1*wc9, 0.f));
        aF[flat] = v;
    }

    // ---- build B fragments (W2 fp16, fragment-major): 8192 uint2, 32/thread -
    #pragma unroll
    for (int it = 0; it < 32; it++) {
        const int flat = it*256 + tid;       // (nt*8 + ks)*32 + lane
        const int lane = flat & 31;
        const int ks   = (flat >> 5) & 7;
        const int nt   = flat >> 8;          // 0..31
        const int k0   = ks*16 + (lane & 3)*2;
        const int col  = nt*8 + (lane >> 2);
        uint2 v;
        v.x = pk2(__ldg(&W2[k0*H2D + col]),     __ldg(&W2[(k0+1)*H2D + col]));
        v.y = pk2(__ldg(&W2[(k0+8)*H2D + col]), __ldg(&W2[(k0+9)*H2D + col]));
        bF[flat] = v;
    }
    __syncthreads();

    // ---- mainloop: warps 4x2 (warp = 32 rows x 128 cols) ----
    const int warp = tid >> 5, lane = tid & 31;
    const int wm = warp & 3, wn = warp >> 2;

    float acc[2][16][4];
    #pragma unroll
    for (int a = 0; a < 2; a++)
        #pragma unroll
        for (int n = 0; n < 16; n++)
            #pragma unroll
            for (int r = 0; r < 4; r++) acc[a][n][r] = 0.f;

    #pragma unroll
    for (int ks = 0; ks < 8; ks++) {
        uint4 a0 = aF[((wm*2+0)*8 + ks)*32 + lane];
        uint4 a1 = aF[((wm*2+1)*8 + ks)*32 + lane];
        #pragma unroll
        for (int nt = 0; nt < 16; nt++) {
            uint2 b = bF[(((wn*16 + nt)*8) + ks)*32 + lane];
            mma_f16(acc[0][nt], &a0.x, &b.x);
            mma_f16(acc[1][nt], &a1.x, &b.x);
        }
    }

    // ---- epilogue: +b2, relu, max over 16 rows of each group, atomicMax ----
    #pragma unroll
    for (int lm = 0; lm < 2; lm++) {
        const int g = g0 + wm*2 + lm;
        if (g >= G) continue;
        const int pt = sPt[wm*2 + lm];
        #pragma unroll
        for (int nt = 0; nt < 16; nt++) {
            float p0 = fmaxf(acc[lm][nt][0], acc[lm][nt][2]);   // rows r, r+8
            float p1 = fmaxf(acc[lm][nt][1], acc[lm][nt][3]);
            #pragma unroll
            for (int o = 4; o < 32; o <<= 1) {
                p0 = fmaxf(p0, __shfl_xor_sync(0xffffffffu, p0, o));
                p1 = fmaxf(p1, __shfl_xor_sync(0xffffffffu, p1, o));
            }
            if (lane < 4) {
                const int col = wn*128 + nt*8 + 2*lane;
                const float m0 = fmaxf(p0 + __ldg(&b2[col]),     0.f);
                const float m1 = fmaxf(p1 + __ldg(&b2[col + 1]), 0.f);
                atomicMax((int*)&g_agg[pt*H2D + col],     __float_as_int(m0));
                atomicMax((int*)&g_agg[pt*H2D + col + 1], __float_as_int(m1));
            }
        }
    }
}

// ---------------------------------------------------------------------------
// Kernel 4: out = g_agg @ Wg + bg via fp16 MMA. 128 blocks, each 128 rows x
// 256 cols, K=256 in two 128-chunks (fragments rebuilt per chunk).
// smem: aF uint4[2048] @0 | bF uint2[8192] @8192  (96 KB)
// ---------------------------------------------------------------------------
#define GEMM_SMEM_BYTES (24576*4)

__global__ __launch_bounds__(256, 1)
void gemm_kernel(const float* __restrict__ Wg,
                 const float* __restrict__ bgv,
                 float* __restrict__ out)
{
    const int tid = threadIdx.x;
    const int rb  = blockIdx.x * 128;

    uint4* aF = reinterpret_cast<uint4*>(dsm);
    uint2* bF = reinterpret_cast<uint2*>(dsm + 8192);

    const int warp = tid >> 5, lane = tid & 31;
    const int wm = warp & 3, wn = warp >> 2;

    float acc[2][16][4];
    #pragma unroll
    for (int a = 0; a < 2; a++)
        #pragma unroll
        for (int n = 0; n < 16; n++)
            #pragma unroll
            for (int r = 0; r < 4; r++) acc[a][n][r] = 0.f;

    for (int kc = 0; kc < H2D; kc += 128) {
        // build A fragments from g_agg
        #pragma unroll
        for (int it = 0; it < 8; it++) {
            const int flat = it*256 + tid;
            const int ln = flat & 31;
            const int ks = (flat >> 5) & 7;
            const int mt = flat >> 8;
            const int R0 = rb + mt*16 + (ln >> 2);
            const int R1 = R0 + 8;
            const int k0 = kc + ks*16 + (ln & 3)*2;
            const float2 p00 = *(const float2*)&g_agg[R0*H2D + k0];
            const float2 p01 = *(const float2*)&g_agg[R0*H2D + k0 + 8];
            const float2 p10 = *(const float2*)&g_agg[R1*H2D + k0];
            const float2 p11 = *(const float2*)&g_agg[R1*H2D + k0 + 8];
            uint4 v;
            v.x = pk2(p00.x, p00.y);
            v.y = pk2(p10.x, p10.y);
            v.z = pk2(p01.x, p01.y);
            v.w = pk2(p11.x, p11.y);
            aF[flat] = v;
        }
        // build B fragments from Wg
        #pragma unroll
        for (int it = 0; it < 32; it++) {
            const int flat = it*256 + tid;
            const int ln = flat & 31;
            const int ks = (flat >> 5) & 7;
            const int nt = flat >> 8;
            const int k0 = kc + ks*16 + (ln & 3)*2;
            const int col = nt*8 + (ln >> 2);
            uint2 v;
            v.x = pk2(__ldg(&Wg[k0*GOUTD + col]),     __ldg(&Wg[(k0+1)*GOUTD + col]));
            v.y = pk2(__ldg(&Wg[(k0+8)*GOUTD + col]), __ldg(&Wg[(k0+9)*GOUTD + col]));
            bF[flat] = v;
        }
        __syncthreads();

        #pragma unroll
        for (int ks = 0; ks < 8; ks++) {
            uint4 a0 = aF[((wm*2+0)*8 + ks)*32 + lane];
            uint4 a1 = aF[((wm*2+1)*8 + ks)*32 + lane];
            #pragma unroll
            for (int nt = 0; nt < 16; nt++) {
                uint2 b = bF[(((wn*16 + nt)*8) + ks)*32 + lane];
                mma_f16(acc[0][nt], &a0.x, &b.x);
                mma_f16(acc[1][nt], &a1.x, &b.x);
            }
        }
        __syncthreads();
    }

    // epilogue: + bias, store
    #pragma unroll
    for (int lm = 0; lm < 2; lm++) {
        const int row = rb + (wm*2 + lm)*16 + (lane >> 2);
        #pragma unroll
        for (int nt = 0; nt < 16; nt++) {
            const int col = wn*128 + nt*8 + (lane & 3)*2;
            const float bg0 = __ldg(&bgv[col]);
            const float bg1 = __ldg(&bgv[col + 1]);
            *(float2*)&out[row*GOUTD + col] =
                make_float2(acc[lm][nt][0] + bg0, acc[lm][nt][1] + bg1);
            *(float2*)&out[(row+8)*GOUTD + col] =
                make_float2(acc[lm][nt][2] + bg0, acc[lm][nt][3] + bg1);
        }
    }
}

// ---------------------------------------------------------------------------
// Kernel 5: gather x_dst / pos_dst / batch_dst from fps indices
// ---------------------------------------------------------------------------
__global__ __launch_bounds__(256)
void gather_kernel(const float* __restrict__ pos,
                   float* __restrict__ out)
{
    const int s   = blockIdx.x;
    const int tid = threadIdx.x;
    const int b   = s >> 9;
    const int m   = s & 511;
    const int gi  = b*NPTS + g_fps[b*MS + m];

    const float* x_all = out;
    float* xd = out + NTOT*GOUTD;
    float* pd = xd  + BGR*MS*GOUTD;
    float* bd = pd  + BGR*MS*3;

    xd[s*GOUTD + tid] = x_all[gi*GOUTD + tid];
    if (tid < 3)  pd[s*3 + tid] = pos[gi*3 + tid];
    if (tid == 3) bd[s] = (float)b;
}

// ---------------------------------------------------------------------------
extern "C" void kernel_launch(void* const* d_in, const int* in_sizes, int n_in,
                              void* d_out, int out_size)
{
    (void)in_sizes; (void)n_in; (void)out_size;
    const float* x   = (const float*)d_in[0];
    const float* pos = (const float*)d_in[1];
    const float* W1  = (const float*)d_in[3];
    const float* b1  = (const float*)d_in[4];
    const float* W2  = (const float*)d_in[5];
    const float* b2  = (const float*)d_in[6];
    const float* Wg  = (const float*)d_in[7];
    const float* bg  = (const float*)d_in[8];
    float* out = (float*)d_out;

    static int smem_set = 0;
    if (!smem_set) {
        cudaFuncSetAttribute(edge_kernel,
                             cudaFuncAttributeMaxDynamicSharedMemorySize,
                             EDGE_SMEM_BYTES);
        cudaFuncSetAttribute(gemm_kernel,
                             cudaFuncAttributeMaxDynamicSharedMemorySize,
                             GEMM_SMEM_BYTES);
        smem_set = 1;
    }

    prep_kernel<<<NTOT/2 + 64 + 1024, 256>>>(x, pos, W1, b1);
    scan_kernel<<<1, 1024>>>();
    edge_kernel<<<BGR + GMAX/8, 256, EDGE_SMEM_BYTES>>>(pos, W1, W2, b2);
    gemm_kernel<<<NTOT/128, 256, GEMM_SMEM_BYTES>>>(Wg, bg, out);
    gather_kernel<<<BGR*MS, 256>>>(pos, out);
}